// round 3
// baseline (speedup 1.0000x reference)
#include <cuda_runtime.h>
#include <math.h>

#define HID   32
#define LEN   32768
#define HOP   256
#define KL    128
#define OUTC  64
#define BATCH 16

#define HSS 268   // hs row stride (264 needed, mod 4 == 0 for float4 rows)
#define XSS 260   // xs row stride (258 needed, mod 4 == 0)

// Scratch: kernel tensor transposed+padded to [b][l][i][o][4] for coalesced loads
// and single-LDS.128 per (i,o) in the main kernel.
__device__ float g_kt[(size_t)BATCH * KL * HID * OUTC * 4];  // 67 MB

__device__ __forceinline__ float fast_tanh(float x) {
    float r; asm("tanh.approx.f32 %0, %1;" : "=f"(r) : "f"(x)); return r;
}
__device__ __forceinline__ float fast_ex2(float x) {
    float r; asm("ex2.approx.f32 %0, %1;" : "=f"(r) : "f"(x)); return r;
}
__device__ __forceinline__ float fast_rcp(float x) {
    float r; asm("rcp.approx.f32 %0, %1;" : "=f"(r) : "f"(x)); return r;
}

// ---------------------------------------------------------------------------
// Pass 1: kernel[b, i, o, k, l] (l fastest) -> g_kt[b][l][ i*256 + o*4 + k ]
// ---------------------------------------------------------------------------
__global__ void transpose_kernel_tensor(const float* __restrict__ kin) {
    __shared__ float tile[32][33];
    int b  = blockIdx.z;
    int m0 = blockIdx.x * 32;   // 192 tiles over m = 6144 (i*192 + o*3 + k)
    int l0 = blockIdx.y * 32;   // 4 tiles over l = 128
    int tx = threadIdx.x, ty = threadIdx.y;
    const float* src = kin + (size_t)b * 6144 * 128;
    float*       dst = g_kt + (size_t)b * 128 * 8192;
#pragma unroll
    for (int r = 0; r < 4; r++) {
        int m = m0 + ty + r * 8;
        tile[ty + r * 8][tx] = src[(size_t)m * 128 + l0 + tx];   // coalesced along l
    }
    __syncthreads();
#pragma unroll
    for (int r = 0; r < 4; r++) {
        int l = l0 + ty + r * 8;
        int m = m0 + tx;
        int mp = (m / 3) * 4 + (m % 3);        // padded index
        dst[(size_t)l * 8192 + mp] = tile[tx][ty + r * 8];
    }
}

// ---------------------------------------------------------------------------
// Pass 2: fused leaky -> dilated conv -> leaky -> LVC -> gate -> +residual.
// One CTA per (l chunk, batch). 256 threads, ~110 KB smem, 2 CTA/SM.
// ---------------------------------------------------------------------------
__global__ __launch_bounds__(256, 2)
void lvc_block_kernel(const float* __restrict__ hidden,
                      const float* __restrict__ bias,
                      const float* __restrict__ conv_w,
                      const float* __restrict__ conv_b,
                      float* __restrict__ out) {
    extern __shared__ float sm[];
    float* ks    = sm;                     // 8192 : ks[i*256 + o*4 + k] (k=3 pad)
    float* wt    = ks + 8192;              // 3072 : wt[(ci*3+k)*32 + c]
    float* biasS = wt + 3072;              // 64
    float* cbS   = biasS + 64;             // 32
    float* hs    = cbS + 32;               // 32*268 : leaky(hidden), hs[c][u] <-> g = cs-4+u
    float* xs    = hs + 32 * HSS;          // 32*260 : conv out, xs[c][u] <-> chunk pos u-1

    const int tid = threadIdx.x;
    const int l = blockIdx.x, b = blockIdx.y;
    const int cs = l * HOP;

    // --- LVC filter: coalesced float4 copy of 32 KB ---
    {
        const float4* ktsrc = (const float4*)(g_kt + ((size_t)b * KL + l) * 8192);
        float4* ksd = (float4*)ks;
        for (int idx = tid; idx < 2048; idx += 256) ksd[idx] = ktsrc[idx];
    }
    // --- Conv weights transposed so lane (= out channel) is contiguous ---
    for (int idx = tid; idx < 3072; idx += 256) {
        int c = idx / 96, r = idx % 96;          // r = ci*3 + k
        wt[r * 32 + c] = conv_w[idx];
    }
    if (tid < 64) biasS[tid] = bias[((size_t)b * 64 + tid) * 128 + l];
    if (tid < 32) cbS[tid]   = conv_b[tid];

    // --- Load leaky(hidden) halo tile [32][268], zero outside [0, LEN) ---
    const float* hidB = hidden + (size_t)b * HID * LEN;
    for (int idx = tid; idx < 32 * HSS; idx += 256) {
        int c = idx / HSS, u = idx % HSS;
        int g = cs - 4 + u;
        float v = (g >= 0 && g < LEN) ? hidB[(size_t)c * LEN + g] : 0.f;
        hs[idx] = (v >= 0.f) ? v : 0.2f * v;
    }
    __syncthreads();

    // --- Dilated conv: thread = (c = tid&31, tb = tid>>5), 32 aligned outputs ---
    // Output chunk pos p = tb*32 + t; h tap at pos p+3(k-1) lives at hs index p+1+3k.
    {
        const int c  = tid & 31;
        const int tb = tid >> 5;               // constant per warp -> hs reads broadcast
        float acc[32];
#pragma unroll
        for (int t = 0; t < 32; t++) acc[t] = 0.f;
        for (int ci = 0; ci < 32; ci++) {
            float w0 = wt[(ci * 3 + 0) * 32 + c];
            float w1 = wt[(ci * 3 + 1) * 32 + c];
            float w2 = wt[(ci * 3 + 2) * 32 + c];
            const float* hrow = hs + ci * HSS + tb * 32;   // 16B aligned
            {
                float h0[24];
#pragma unroll
                for (int jj = 0; jj < 6; jj++) ((float4*)h0)[jj] = ((const float4*)hrow)[jj];
#pragma unroll
                for (int t = 0; t < 16; t++)
                    acc[t] += w0 * h0[t + 1] + w1 * h0[t + 4] + w2 * h0[t + 7];
            }
            {
                float h1[24];
#pragma unroll
                for (int jj = 0; jj < 6; jj++) ((float4*)h1)[jj] = ((const float4*)(hrow + 16))[jj];
#pragma unroll
                for (int t = 0; t < 16; t++)
                    acc[16 + t] += w0 * h1[t + 1] + w1 * h1[t + 4] + w2 * h1[t + 7];
            }
        }
        float cb = cbS[c];
        float* xrow = xs + c * XSS + tb * 32 + 1;   // xs index u = p + 1
#pragma unroll
        for (int t = 0; t < 32; t++) {
            float v = acc[t] + cb;
            xrow[t] = (v >= 0.f) ? v : 0.2f * v;    // p in [0,256) always inside [0,LEN)
        }
        // Boundary LVC-window positions p = -1 and p = 256 (zero outside [0,LEN))
        if (tid < 64) {
            int c2 = tid & 31;
            int p  = (tid < 32) ? -1 : 256;
            int u0 = p + 1;                         // 0 or 257; taps at u0 + 3k
            float accv = 0.f;
            for (int ci = 0; ci < 32; ci++) {
                const float* hr = hs + ci * HSS + u0;
                accv += wt[(ci * 3 + 0) * 32 + c2] * hr[0]
                      + wt[(ci * 3 + 1) * 32 + c2] * hr[3]
                      + wt[(ci * 3 + 2) * 32 + c2] * hr[6];
            }
            float v = accv + cbS[c2];
            v = (v >= 0.f) ? v : 0.2f * v;
            int gp = cs + p;
            xs[c2 * XSS + u0] = (gp >= 0 && gp < LEN) ? v : 0.f;
        }
    }
    __syncthreads();

    // --- LVC: thread = (ob = tid&7, sb = tid>>3); o = ob + 8*oi, s = 8*sb + j ---
    const int ob = tid & 7;
    const int sb = tid >> 3;
    const int s0 = sb * 8;
    float a[8][8];
#pragma unroll
    for (int oi = 0; oi < 8; oi++)
#pragma unroll
        for (int j = 0; j < 8; j++) a[oi][j] = 0.f;

    const float4* ks4 = (const float4*)ks;
    for (int i = 0; i < 32; i++) {
        // x at chunk pos s+k-1 lives at xs index s+k -> xv[t] = xs[i][s0+t], t = j+k
        float xv[12];
        const float4* xr = (const float4*)(xs + i * XSS + s0);
#pragma unroll
        for (int jj = 0; jj < 3; jj++) ((float4*)xv)[jj] = xr[jj];
#pragma unroll
        for (int oi = 0; oi < 8; oi++) {
            float4 kv = ks4[i * 64 + ob + 8 * oi];   // one LDS.128, conflict-free
#pragma unroll
            for (int j = 0; j < 8; j++)
                a[oi][j] += kv.x * xv[j] + kv.y * xv[j + 1] + kv.z * xv[j + 2];
        }
    }

    // --- Gate + residual. Pairs (o, o+32) = (a[oi], a[oi+4]) ---
    const float* hidC = hidB + cs;
    float* outC = out + (size_t)b * HID * LEN + cs;
    const float LOG2E = 1.4426950408889634f;
#pragma unroll
    for (int oi = 0; oi < 4; oi++) {
        int o = ob + 8 * oi;                 // output channel 0..31
        float bg = biasS[o], bh = biasS[o + 32];
        float4 r0 = *(const float4*)(hidC + (size_t)o * LEN + s0);
        float4 r1 = *(const float4*)(hidC + (size_t)o * LEN + s0 + 4);
        float res[8] = {r0.x, r0.y, r0.z, r0.w, r1.x, r1.y, r1.z, r1.w};
        float yo[8];
#pragma unroll
        for (int j = 0; j < 8; j++) {
            float gv = a[oi][j] + bg;
            float hv = a[oi + 4][j] + bh;
            float sig = fast_rcp(1.f + fast_ex2(-LOG2E * gv));
            yo[j] = res[j] + sig * fast_tanh(hv);
        }
        *(float4*)(outC + (size_t)o * LEN + s0)     = make_float4(yo[0], yo[1], yo[2], yo[3]);
        *(float4*)(outC + (size_t)o * LEN + s0 + 4) = make_float4(yo[4], yo[5], yo[6], yo[7]);
    }
}

// ---------------------------------------------------------------------------
extern "C" void kernel_launch(void* const* d_in, const int* in_sizes, int n_in,
                              void* d_out, int out_size) {
    const float* hidden = (const float*)d_in[0];
    const float* kern   = (const float*)d_in[1];
    const float* bias   = (const float*)d_in[2];
    const float* conv_w = (const float*)d_in[3];
    const float* conv_b = (const float*)d_in[4];
    float* out = (float*)d_out;

    transpose_kernel_tensor<<<dim3(192, 4, 16), dim3(32, 8)>>>(kern);

    int smem_bytes = (8192 + 3072 + 64 + 32 + 32 * HSS + 32 * XSS) * 4;  // 113,024 B
    cudaFuncSetAttribute(lvc_block_kernel,
                         cudaFuncAttributeMaxDynamicSharedMemorySize, smem_bytes);
    lvc_block_kernel<<<dim3(KL, BATCH), 256, smem_bytes>>>(hidden, bias, conv_w, conv_b, out);
}

// round 5
// speedup vs baseline: 1.1293x; 1.1293x over previous
#include <cuda_runtime.h>
#include <stdint.h>

#define HID   32
#define LEN   32768
#define BATCH 16
#define KLCH  128

#define HSS 136   // hs row stride (floats)
#define XSS 132   // xs row stride (floats)
#define DSS 132   // ds row stride (floats)
#define WTS 100   // weight row stride (floats): conflict-free for B-fragment loads

// smem float offsets
#define OF_WT1  0                  // 32 x WTS  = 3200
#define OF_WT2  3200               // 64 x WTS  = 6400
#define OF_BIAS 9600               // 64
#define OF_CB   9664               // 32
#define OF_HS   9696               // 32 x 136 = 4352
#define OF_XS   14048              // 32 x 132 = 4224
#define OF_DS   OF_HS              // alias (64 x 132 = 8448 <= 8576)
#define SMEM_FLOATS 18272          // 73,088 bytes

// kernel tensor pre-transposed: g_kt[b][l][m], m = i*192 + o*3 + k
__device__ float g_kt[(size_t)BATCH * KLCH * 6144];

__device__ __forceinline__ float tf32r(float x) {
    uint32_t r; asm("cvt.rna.tf32.f32 %0, %1;" : "=r"(r) : "f"(x)); return __uint_as_float(r);
}
__device__ __forceinline__ float fast_tanh(float x) { float r; asm("tanh.approx.f32 %0, %1;" : "=f"(r) : "f"(x)); return r; }
__device__ __forceinline__ float fast_ex2(float x)  { float r; asm("ex2.approx.f32 %0, %1;"  : "=f"(r) : "f"(x)); return r; }
__device__ __forceinline__ float fast_rcp(float x)  { float r; asm("rcp.approx.f32 %0, %1;"  : "=f"(r) : "f"(x)); return r; }

__device__ __forceinline__ void mma_tf32(float c[4],
                                         uint32_t a0, uint32_t a1, uint32_t a2, uint32_t a3,
                                         uint32_t b0, uint32_t b1) {
    asm volatile(
        "mma.sync.aligned.m16n8k8.row.col.f32.tf32.tf32.f32 "
        "{%0,%1,%2,%3}, {%4,%5,%6,%7}, {%8,%9}, {%0,%1,%2,%3};"
        : "+f"(c[0]), "+f"(c[1]), "+f"(c[2]), "+f"(c[3])
        : "r"(a0), "r"(a1), "r"(a2), "r"(a3), "r"(b0), "r"(b1));
}

// ---------------------------------------------------------------------------
// Pass 1: kernel[b, i, o, k, l] (l fastest) -> g_kt[b][l][i*192 + o*3 + k]
// ---------------------------------------------------------------------------
__global__ void transpose_kernel_tensor(const float* __restrict__ kin) {
    __shared__ float tile[32][33];
    int b  = blockIdx.z;
    int m0 = blockIdx.x * 32;
    int l0 = blockIdx.y * 32;
    int tx = threadIdx.x, ty = threadIdx.y;
    const float* src = kin + (size_t)b * 6144 * 128;
    float*       dst = g_kt + (size_t)b * 128 * 6144;
#pragma unroll
    for (int r = 0; r < 4; r++) {
        int m = m0 + ty + r * 8;
        tile[ty + r * 8][tx] = src[(size_t)m * 128 + l0 + tx];
    }
    __syncthreads();
#pragma unroll
    for (int r = 0; r < 4; r++) {
        int l = l0 + ty + r * 8;
        dst[(size_t)l * 6144 + m0 + tx] = tile[tx][ty + r * 8];
    }
}

// ---------------------------------------------------------------------------
// Main fused kernel: one CTA per (128-position half-chunk, batch). 256 thr.
// ---------------------------------------------------------------------------
__global__ __launch_bounds__(256, 2)
void lvc_mma_kernel(const float* __restrict__ hidden,
                    const float* __restrict__ bias,
                    const float* __restrict__ conv_w,
                    const float* __restrict__ conv_b,
                    float* __restrict__ out) {
    extern __shared__ float sm[];
    float* wt1f  = sm + OF_WT1;
    float* wt2f  = sm + OF_WT2;
    float* biasS = sm + OF_BIAS;
    float* cbS   = sm + OF_CB;
    float* hsf   = sm + OF_HS;
    float* xsf   = sm + OF_XS;
    float* dsf   = sm + OF_DS;     // aliases hs (+xs tail) region

    const int tid  = threadIdx.x;
    const int wid  = tid >> 5;
    const int lane = tid & 31;
    const int half = blockIdx.x;      // 0..255
    const int b    = blockIdx.y;
    const int s0   = half * 128;
    const int l    = half >> 1;

    // ---- P0: stage weights + inputs ----
    for (int idx = tid; idx < 3072; idx += 256) {        // conv W [co][ci*3+k]
        int co = idx / 96, kk = idx - co * 96;
        wt1f[co * WTS + kk] = tf32r(conv_w[idx]);
    }
    {
        const float* ksrc = g_kt + ((size_t)b * KLCH + l) * 6144;
        for (int m = tid; m < 6144; m += 256) {          // LVC W -> wt2[o][i*3+k]
            int i = m / 192, r = m - i * 192, o = r / 3, k = r - o * 3;
            wt2f[o * WTS + i * 3 + k] = tf32r(ksrc[m]);
        }
    }
    if (tid < 64) biasS[tid] = bias[((size_t)b * 64 + tid) * KLCH + l];
    if (tid < 32) cbS[tid]   = conv_b[tid];
    const float* hidB = hidden + (size_t)b * HID * LEN;
    for (int idx = tid; idx < 32 * HSS; idx += 256) {    // leaky(hidden) halo
        int c = idx / HSS, v = idx - c * HSS;
        int g = s0 - 4 + v;
        float x = (g >= 0 && g < LEN) ? hidB[(size_t)c * LEN + g] : 0.f;
        hsf[idx] = tf32r((x >= 0.f) ? x : 0.2f * x);
    }
    __syncthreads();

    const int tq = lane & 3;      // threadID_in_group
    const int tr = lane >> 2;     // groupID
    const int m0 = wid * 16;

    // ---- Stage 1: conv GEMM  D1[m][c] = sum_kk A1[m][kk] * W1[c][kk] ----
    // A1[m][ci*3+k] = hs[ci][m + 3k]   (rows m=0..127 <-> p = s0-1+m)
    {
        float c1[4][4];
#pragma unroll
        for (int nt = 0; nt < 4; nt++)
#pragma unroll
            for (int j = 0; j < 4; j++) c1[nt][j] = 0.f;

#pragma unroll
        for (int ks = 0; ks < 12; ks++) {
            int kk0 = ks * 8 + tq;
            int ci0 = kk0 / 3, kr0 = kk0 - ci0 * 3;
            int kk1 = kk0 + 4;
            int ci1 = kk1 / 3, kr1 = kk1 - ci1 * 3;
            int base = m0 + tr;
            uint32_t a0 = __float_as_uint(hsf[ci0 * HSS + base     + 3 * kr0]);
            uint32_t a1 = __float_as_uint(hsf[ci0 * HSS + base + 8 + 3 * kr0]);
            uint32_t a2 = __float_as_uint(hsf[ci1 * HSS + base     + 3 * kr1]);
            uint32_t a3 = __float_as_uint(hsf[ci1 * HSS + base + 8 + 3 * kr1]);
#pragma unroll
            for (int nt = 0; nt < 4; nt++) {
                const float* wr = wt1f + (nt * 8 + tr) * WTS + ks * 8 + tq;
                mma_tf32(c1[nt], a0, a1, a2, a3,
                         __float_as_uint(wr[0]), __float_as_uint(wr[4]));
            }
        }
        // write xs[c][m] = leaky(D1 + cb), zero when p = s0-1+m < 0
        bool z0 = (s0 == 0) && (m0 + tr == 0);
#pragma unroll
        for (int nt = 0; nt < 4; nt++) {
            int c = nt * 8 + 2 * tq;
            float v00 = c1[nt][0] + cbS[c];
            float v01 = c1[nt][1] + cbS[c + 1];
            float v10 = c1[nt][2] + cbS[c];
            float v11 = c1[nt][3] + cbS[c + 1];
            v00 = tf32r((v00 >= 0.f) ? v00 : 0.2f * v00);
            v01 = tf32r((v01 >= 0.f) ? v01 : 0.2f * v01);
            v10 = tf32r((v10 >= 0.f) ? v10 : 0.2f * v10);
            v11 = tf32r((v11 >= 0.f) ? v11 : 0.2f * v11);
            xsf[c       * XSS + m0 + tr]     = z0 ? 0.f : v00;
            xsf[(c + 1) * XSS + m0 + tr]     = z0 ? 0.f : v01;
            xsf[c       * XSS + m0 + tr + 8] = v10;
            xsf[(c + 1) * XSS + m0 + tr + 8] = v11;
        }
    }
    // scalar tail: rows m = 128, 129 (p = s0+127, s0+128), 32 channels each
    if (tid >= 128 && tid < 192) {
        int posI = (tid - 128) >> 5, c = tid & 31;
        int m = 128 + posI;
        float acc = 0.f;
        for (int ci = 0; ci < 32; ci++) {
            const float* hr = hsf + ci * HSS + m;
            const float* wr = wt1f + c * WTS + ci * 3;
            acc += wr[0] * hr[0] + wr[1] * hr[3] + wr[2] * hr[6];
        }
        float v = acc + cbS[c];
        v = tf32r((v >= 0.f) ? v : 0.2f * v);
        int p = s0 - 1 + m;
        xsf[c * XSS + m] = (p < LEN) ? v : 0.f;
    }
    __syncthreads();

    // ---- Stage 2: LVC GEMM  D2[m][o] = sum_kk A2[m][kk] * W2[o][kk] ----
    // A2[m][i*3+k] = xs[i][m + k]   (rows m=0..127 <-> s = s0+m)
    float c2[8][4];
#pragma unroll
    for (int nt = 0; nt < 8; nt++)
#pragma unroll
        for (int j = 0; j < 4; j++) c2[nt][j] = 0.f;

#pragma unroll
    for (int ks = 0; ks < 12; ks++) {
        int kk0 = ks * 8 + tq;
        int i0 = kk0 / 3, kr0 = kk0 - i0 * 3;
        int kk1 = kk0 + 4;
        int i1 = kk1 / 3, kr1 = kk1 - i1 * 3;
        int base = m0 + tr;
        uint32_t a0 = __float_as_uint(xsf[i0 * XSS + base     + kr0]);
        uint32_t a1 = __float_as_uint(xsf[i0 * XSS + base + 8 + kr0]);
        uint32_t a2 = __float_as_uint(xsf[i1 * XSS + base     + kr1]);
        uint32_t a3 = __float_as_uint(xsf[i1 * XSS + base + 8 + kr1]);
#pragma unroll
        for (int nt = 0; nt < 8; nt++) {
            const float* wr = wt2f + (nt * 8 + tr) * WTS + ks * 8 + tq;
            mma_tf32(c2[nt], a0, a1, a2, a3,
                     __float_as_uint(wr[0]), __float_as_uint(wr[4]));
        }
    }
    __syncthreads();   // xs reads complete before ds (alias) is written

    // ---- transpose D2 through smem (conflict-free STS) ----
#pragma unroll
    for (int nt = 0; nt < 8; nt++) {
        int o = nt * 8 + 2 * tq;
        dsf[o       * DSS + m0 + tr]     = c2[nt][0];
        dsf[(o + 1) * DSS + m0 + tr]     = c2[nt][1];
        dsf[o       * DSS + m0 + tr + 8] = c2[nt][2];
        dsf[(o + 1) * DSS + m0 + tr + 8] = c2[nt][3];
    }
    __syncthreads();

    // ---- epilogue: gate + residual, coalesced float4 I/O ----
    {
        const int o   = tid >> 3;          // 0..31
        const int seg = tid & 7;           // 16 positions each
        const float bg = biasS[o], bh = biasS[o + 32];
        const float* gRow = dsf + o * DSS + seg * 16;
        const float* hRow = dsf + (o + 32) * DSS + seg * 16;
        const float* rRow = hidB + (size_t)o * LEN + s0 + seg * 16;
        float* oRow = out + (size_t)b * HID * LEN + (size_t)o * LEN + s0 + seg * 16;
        const float LOG2E = 1.4426950408889634f;
#pragma unroll
        for (int j = 0; j < 4; j++) {
            float4 gv = *(const float4*)(gRow + j * 4);
            float4 hv = *(const float4*)(hRow + j * 4);
            float4 rv = *(const float4*)(rRow + j * 4);
            float yo[4];
            float gx[4] = {gv.x, gv.y, gv.z, gv.w};
            float hx[4] = {hv.x, hv.y, hv.z, hv.w};
            float rx[4] = {rv.x, rv.y, rv.z, rv.w};
#pragma unroll
            for (int q = 0; q < 4; q++) {
                float sig = fast_rcp(1.f + fast_ex2(-LOG2E * (gx[q] + bg)));
                yo[q] = rx[q] + sig * fast_tanh(hx[q] + bh);
            }
            *(float4*)(oRow + j * 4) = make_float4(yo[0], yo[1], yo[2], yo[3]);
        }
    }
}

// ---------------------------------------------------------------------------
extern "C" void kernel_launch(void* const* d_in, const int* in_sizes, int n_in,
                              void* d_out, int out_size) {
    const float* hidden = (const float*)d_in[0];
    const float* kern   = (const float*)d_in[1];
    const float* bias   = (const float*)d_in[2];
    const float* conv_w = (const float*)d_in[3];
    const float* conv_b = (const float*)d_in[4];
    float* out = (float*)d_out;

    transpose_kernel_tensor<<<dim3(192, 4, 16), dim3(32, 8)>>>(kern);

    int smem_bytes = SMEM_FLOATS * 4;   // 73,088 B
    cudaFuncSetAttribute(lvc_mma_kernel,
                         cudaFuncAttributeMaxDynamicSharedMemorySize, smem_bytes);
    lvc_mma_kernel<<<dim3(256, BATCH), 256, smem_bytes>>>(hidden, bias, conv_w, conv_b, out);
}

// round 6
// speedup vs baseline: 1.5131x; 1.3399x over previous
#include <cuda_runtime.h>
#include <stdint.h>

#define HID   32
#define LEN   32768
#define BATCH 16
#define KLCH  128

#define HSS 136   // hs row stride (floats)
#define XSS 132   // xs row stride (floats)
#define DSS 132   // ds row stride (floats)

// smem float offsets
#define OF_WT1  0                  // 3072 : conv W, fragment order
#define OF_WT2  3072               // 6144 : LVC W, fragment order
#define OF_BIAS 9216               // 64
#define OF_CB   9280               // 32
#define OF_HS   9312               // 32 x 136 = 4352
#define OF_XS   13664              // 32 x 132 = 4224
#define OF_DS   OF_HS              // alias (64 x 132 = 8448 <= 8576)
#define SMEM_FLOATS 17888          // 71,552 bytes

// LVC kernel pre-packed in MMA B-fragment order: g_kt[b][l][f], f in [0,6144)
__device__ __align__(16) float g_kt[(size_t)BATCH * KLCH * 6144];
// conv W pre-packed in fragment order (N=32 variant)
__device__ __align__(16) float g_w1f[3072];

__device__ __forceinline__ float tf32r(float x) {
    uint32_t r; asm("cvt.rna.tf32.f32 %0, %1;" : "=r"(r) : "f"(x)); return __uint_as_float(r);
}
__device__ __forceinline__ float fast_tanh(float x) { float r; asm("tanh.approx.f32 %0, %1;" : "=f"(r) : "f"(x)); return r; }
__device__ __forceinline__ float fast_ex2(float x)  { float r; asm("ex2.approx.f32 %0, %1;"  : "=f"(r) : "f"(x)); return r; }
__device__ __forceinline__ float fast_rcp(float x)  { float r; asm("rcp.approx.f32 %0, %1;"  : "=f"(r) : "f"(x)); return r; }

__device__ __forceinline__ void mma_tf32(float c[4],
                                         uint32_t a0, uint32_t a1, uint32_t a2, uint32_t a3,
                                         float b0, float b1) {
    asm volatile(
        "mma.sync.aligned.m16n8k8.row.col.f32.tf32.tf32.f32 "
        "{%0,%1,%2,%3}, {%4,%5,%6,%7}, {%8,%9}, {%0,%1,%2,%3};"
        : "+f"(c[0]), "+f"(c[1]), "+f"(c[2]), "+f"(c[3])
        : "r"(a0), "r"(a1), "r"(a2), "r"(a3),
          "r"(__float_as_uint(b0)), "r"(__float_as_uint(b1)));
}

// fragment-order index helpers -------------------------------------------------
// stage2 (N=64): f = ((ks*4 + p)*32 + lane)*4 + sub
//   sub: 0 -> (nt=2p, b0) 1 -> (nt=2p, b1) 2 -> (nt=2p+1, b0) 3 -> (nt=2p+1, b1)
//   lane = tq + 4*tr ; b0: kk = ks*8+tq ; b1: kk+4 ; n-row = nt*8 + tr
// stage1 (N=32): f = ((ks*2 + p)*32 + lane)*4 + sub  (p in {0,1}, nt = 2p+(sub>>1))

// conv-W element accessor in frag layout (for scalar tail rows)
__device__ __forceinline__ float w1frag_at(const float* wt1f, int c, int kk) {
    int ks = kk >> 3, r = kk & 7, tq = r & 3, hi = r >> 2;
    int tr = c & 7, nt = c >> 3, p = nt >> 1, odd = nt & 1;
    return wt1f[(((ks * 2 + p) * 32 + tq + 4 * tr) << 2) + odd * 2 + hi];
}

// ---------------------------------------------------------------------------
// Prep 1: kernel[b, i, o, k, l] (l fastest) -> g_kt[b][l][frag f]
// dst-f enumerated contiguously; src m gathered (reads still coalesced along l).
// ---------------------------------------------------------------------------
__global__ void prep_kernel_tensor(const float* __restrict__ kin) {
    __shared__ float tile[32][33];
    int b  = blockIdx.z;
    int f0 = blockIdx.x * 32;
    int l0 = blockIdx.y * 32;
    int tx = threadIdx.x, ty = threadIdx.y;
    const float* src = kin + (size_t)b * 6144 * 128;
    float*       dst = g_kt + (size_t)b * 128 * 6144;
#pragma unroll
    for (int r = 0; r < 4; r++) {
        int f = f0 + ty + r * 8;
        int sub = f & 3, lane = (f >> 2) & 31, rest = f >> 7;
        int p = rest & 3, ks = rest >> 2;
        int tq = lane & 3, tr = lane >> 2;
        int kk = ks * 8 + tq + (sub & 1) * 4;
        int nt = 2 * p + (sub >> 1);
        int o  = nt * 8 + tr;
        int i  = kk / 3, k = kk - 3 * i;
        int m  = i * 192 + o * 3 + k;
        tile[ty + r * 8][tx] = tf32r(src[(size_t)m * 128 + l0 + tx]);
    }
    __syncthreads();
#pragma unroll
    for (int r = 0; r < 4; r++) {
        int l = l0 + ty + r * 8;
        dst[(size_t)l * 6144 + f0 + tx] = tile[tx][ty + r * 8];
    }
}

// Prep 2: conv_w [co][ci*3+k] -> g_w1f frag order (N=32 variant)
__global__ void prep_w1(const float* __restrict__ conv_w) {
    int f = blockIdx.x * 256 + threadIdx.x;
    if (f < 3072) {
        int sub = f & 3, lane = (f >> 2) & 31, rest = f >> 7;
        int p = rest & 1, ks = rest >> 1;
        int tq = lane & 3, tr = lane >> 2;
        int kk = ks * 8 + tq + (sub & 1) * 4;
        int nt = 2 * p + (sub >> 1);
        int co = nt * 8 + tr;
        g_w1f[f] = tf32r(conv_w[co * 96 + kk]);
    }
}

// ---------------------------------------------------------------------------
// Main fused kernel: one CTA per (256-position chunk, batch); 2 sub-halves.
// ---------------------------------------------------------------------------
__global__ __launch_bounds__(256, 2)
void lvc_mma_kernel(const float* __restrict__ hidden,
                    const float* __restrict__ bias,
                    const float* __restrict__ conv_w,
                    const float* __restrict__ conv_b,
                    float* __restrict__ out) {
    extern __shared__ float sm[];
    float* wt1f  = sm + OF_WT1;
    float* wt2f  = sm + OF_WT2;
    float* biasS = sm + OF_BIAS;
    float* cbS   = sm + OF_CB;
    float* hsf   = sm + OF_HS;
    float* xsf   = sm + OF_XS;
    float* dsf   = sm + OF_DS;     // aliases hs/xs region

    const int tid  = threadIdx.x;
    const int wid  = tid >> 5;
    const int lane = tid & 31;
    const int l    = blockIdx.x;      // chunk 0..127
    const int b    = blockIdx.y;

    // ---- stage weights (raw vector copies; already tf32-rounded + frag-ordered) ----
    {
        const float4* w2s = (const float4*)(g_kt + ((size_t)b * KLCH + l) * 6144);
        float4* w2d = (float4*)wt2f;
        for (int i = tid; i < 1536; i += 256) w2d[i] = w2s[i];
        const float4* w1s = (const float4*)g_w1f;
        float4* w1d = (float4*)wt1f;
        for (int i = tid; i < 768; i += 256) w1d[i] = w1s[i];
    }
    if (tid < 64) biasS[tid] = bias[((size_t)b * 64 + tid) * KLCH + l];
    if (tid < 32) cbS[tid]   = conv_b[tid];
    const float* hidB = hidden + (size_t)b * HID * LEN;

    const int tq = lane & 3;      // threadID_in_group
    const int tr = lane >> 2;     // groupID
    const int m0 = wid * 16;

    for (int sub = 0; sub < 2; sub++) {
        const int s0 = l * 256 + sub * 128;
        __syncthreads();   // ds/epilogue of previous sub done before hs overwrite

        // ---- hs: leaky(hidden) halo, hs[c][v] <-> g = s0-4+v ----
        for (int idx = tid; idx < 32 * HSS; idx += 256) {
            int c = idx / HSS, v = idx - c * HSS;
            int g = s0 - 4 + v;
            float x = (g >= 0 && g < LEN) ? hidB[(size_t)c * LEN + g] : 0.f;
            hsf[idx] = tf32r((x >= 0.f) ? x : 0.2f * x);
        }
        __syncthreads();

        // ---- Stage 1: conv GEMM, rows m=0..127 <-> p = s0-1+m ----
        {
            float c1[4][4];
#pragma unroll
            for (int nt = 0; nt < 4; nt++)
#pragma unroll
                for (int j = 0; j < 4; j++) c1[nt][j] = 0.f;

#pragma unroll
            for (int ks = 0; ks < 12; ks++) {
                int kk0 = ks * 8 + tq;
                int ci0 = kk0 / 3, kr0 = kk0 - ci0 * 3;
                int kk1 = kk0 + 4;
                int ci1 = kk1 / 3, kr1 = kk1 - ci1 * 3;
                int base = m0 + tr;
                uint32_t a0 = __float_as_uint(hsf[ci0 * HSS + base     + 3 * kr0]);
                uint32_t a1 = __float_as_uint(hsf[ci0 * HSS + base + 8 + 3 * kr0]);
                uint32_t a2 = __float_as_uint(hsf[ci1 * HSS + base     + 3 * kr1]);
                uint32_t a3 = __float_as_uint(hsf[ci1 * HSS + base + 8 + 3 * kr1]);
                const float4* bp = (const float4*)wt1f + (ks * 2) * 32 + lane;
                float4 q0 = bp[0];
                float4 q1 = bp[32];
                mma_tf32(c1[0], a0, a1, a2, a3, q0.x, q0.y);
                mma_tf32(c1[1], a0, a1, a2, a3, q0.z, q0.w);
                mma_tf32(c1[2], a0, a1, a2, a3, q1.x, q1.y);
                mma_tf32(c1[3], a0, a1, a2, a3, q1.z, q1.w);
            }
            bool z0 = (s0 == 0) && (m0 + tr == 0);
#pragma unroll
            for (int nt = 0; nt < 4; nt++) {
                int c = nt * 8 + 2 * tq;
                float v00 = c1[nt][0] + cbS[c];
                float v01 = c1[nt][1] + cbS[c + 1];
                float v10 = c1[nt][2] + cbS[c];
                float v11 = c1[nt][3] + cbS[c + 1];
                v00 = tf32r((v00 >= 0.f) ? v00 : 0.2f * v00);
                v01 = tf32r((v01 >= 0.f) ? v01 : 0.2f * v01);
                v10 = tf32r((v10 >= 0.f) ? v10 : 0.2f * v10);
                v11 = tf32r((v11 >= 0.f) ? v11 : 0.2f * v11);
                xsf[c       * XSS + m0 + tr]     = z0 ? 0.f : v00;
                xsf[(c + 1) * XSS + m0 + tr]     = z0 ? 0.f : v01;
                xsf[c       * XSS + m0 + tr + 8] = v10;
                xsf[(c + 1) * XSS + m0 + tr + 8] = v11;
            }
        }
        // scalar tail rows m = 128, 129 (p = s0+127, s0+128)
        if (tid >= 128 && tid < 192) {
            int posI = (tid - 128) >> 5, c = tid & 31;
            int m = 128 + posI;
            float acc = 0.f;
            for (int ci = 0; ci < 32; ci++) {
                const float* hr = hsf + ci * HSS + m;
                acc += w1frag_at(wt1f, c, ci * 3 + 0) * hr[0]
                     + w1frag_at(wt1f, c, ci * 3 + 1) * hr[3]
                     + w1frag_at(wt1f, c, ci * 3 + 2) * hr[6];
            }
            float v = acc + cbS[c];
            v = tf32r((v >= 0.f) ? v : 0.2f * v);
            int p = s0 - 1 + m;
            xsf[c * XSS + m] = (p < LEN) ? v : 0.f;
        }
        __syncthreads();

        // ---- Stage 2: LVC GEMM, rows m <-> s = s0+m ----
        float c2[8][4];
#pragma unroll
        for (int nt = 0; nt < 8; nt++)
#pragma unroll
            for (int j = 0; j < 4; j++) c2[nt][j] = 0.f;

#pragma unroll
        for (int ks = 0; ks < 12; ks++) {
            int kk0 = ks * 8 + tq;
            int i0 = kk0 / 3, kr0 = kk0 - i0 * 3;
            int kk1 = kk0 + 4;
            int i1 = kk1 / 3, kr1 = kk1 - i1 * 3;
            int base = m0 + tr;
            uint32_t a0 = __float_as_uint(xsf[i0 * XSS + base     + kr0]);
            uint32_t a1 = __float_as_uint(xsf[i0 * XSS + base + 8 + kr0]);
            uint32_t a2 = __float_as_uint(xsf[i1 * XSS + base     + kr1]);
            uint32_t a3 = __float_as_uint(xsf[i1 * XSS + base + 8 + kr1]);
            const float4* bp = (const float4*)wt2f + (ks * 4) * 32 + lane;
            float4 q0 = bp[0];
            float4 q1 = bp[32];
            float4 q2 = bp[64];
            float4 q3 = bp[96];
            mma_tf32(c2[0], a0, a1, a2, a3, q0.x, q0.y);
            mma_tf32(c2[1], a0, a1, a2, a3, q0.z, q0.w);
            mma_tf32(c2[2], a0, a1, a2, a3, q1.x, q1.y);
            mma_tf32(c2[3], a0, a1, a2, a3, q1.z, q1.w);
            mma_tf32(c2[4], a0, a1, a2, a3, q2.x, q2.y);
            mma_tf32(c2[5], a0, a1, a2, a3, q2.z, q2.w);
            mma_tf32(c2[6], a0, a1, a2, a3, q3.x, q3.y);
            mma_tf32(c2[7], a0, a1, a2, a3, q3.z, q3.w);
        }
        __syncthreads();   // xs reads complete before ds (alias) is written

        // ---- transpose D2 through smem ----
#pragma unroll
        for (int nt = 0; nt < 8; nt++) {
            int o = nt * 8 + 2 * tq;
            dsf[o       * DSS + m0 + tr]     = c2[nt][0];
            dsf[(o + 1) * DSS + m0 + tr]     = c2[nt][1];
            dsf[o       * DSS + m0 + tr + 8] = c2[nt][2];
            dsf[(o + 1) * DSS + m0 + tr + 8] = c2[nt][3];
        }
        __syncthreads();

        // ---- epilogue: gate + residual, coalesced float4 I/O ----
        {
            const int o   = tid >> 3;          // 0..31
            const int seg = tid & 7;           // 16 positions each
            const float bg = biasS[o], bh = biasS[o + 32];
            const float* gRow = dsf + o * DSS + seg * 16;
            const float* hRow = dsf + (o + 32) * DSS + seg * 16;
            const float* rRow = hidB + (size_t)o * LEN + s0 + seg * 16;
            float* oRow = out + (size_t)b * HID * LEN + (size_t)o * LEN + s0 + seg * 16;
            const float LOG2E = 1.4426950408889634f;
#pragma unroll
            for (int j = 0; j < 4; j++) {
                float4 gv = *(const float4*)(gRow + j * 4);
                float4 hv = *(const float4*)(hRow + j * 4);
                float4 rv = *(const float4*)(rRow + j * 4);
                float gx[4] = {gv.x, gv.y, gv.z, gv.w};
                float hx[4] = {hv.x, hv.y, hv.z, hv.w};
                float rx[4] = {rv.x, rv.y, rv.z, rv.w};
                float yo[4];
#pragma unroll
                for (int q = 0; q < 4; q++) {
                    float sig = fast_rcp(1.f + fast_ex2(-LOG2E * (gx[q] + bg)));
                    yo[q] = rx[q] + sig * fast_tanh(hx[q] + bh);
                }
                *(float4*)(oRow + j * 4) = make_float4(yo[0], yo[1], yo[2], yo[3]);
            }
        }
    }
}

// ---------------------------------------------------------------------------
extern "C" void kernel_launch(void* const* d_in, const int* in_sizes, int n_in,
                              void* d_out, int out_size) {
    const float* hidden = (const float*)d_in[0];
    const float* kern   = (const float*)d_in[1];
    const float* bias   = (const float*)d_in[2];
    const float* conv_w = (const float*)d_in[3];
    const float* conv_b = (const float*)d_in[4];
    float* out = (float*)d_out;

    prep_w1<<<12, 256>>>(conv_w);
    prep_kernel_tensor<<<dim3(192, 4, 16), dim3(32, 8)>>>(kern);

    int smem_bytes = SMEM_FLOATS * 4;   // 71,552 B
    cudaFuncSetAttribute(lvc_mma_kernel,
                         cudaFuncAttributeMaxDynamicSharedMemorySize, smem_bytes);
    lvc_mma_kernel<<<dim3(KLCH, BATCH), 256, smem_bytes>>>(hidden, bias, conv_w, conv_b, out);
}

// round 7
// speedup vs baseline: 1.6616x; 1.0981x over previous
#include <cuda_runtime.h>
#include <stdint.h>

#define HID   32
#define LEN   32768
#define BATCH 16
#define KLCH  128

#define HSS 136   // hs row stride (floats); 34 float4 granules per row
#define XSS 132   // xs row stride (floats)

// smem float offsets
#define OF_WT1  0                  // 3072 : conv W, fragment order
#define OF_WT2  3072               // 6144 : LVC W, fragment order
#define OF_BIAS 9216               // 64
#define OF_CB   9280               // 32
#define OF_HS0  9312               // 32 x 136 = 4352
#define OF_HS1  13664              // 32 x 136 = 4352
#define OF_XS   18016              // 32 x 132 = 4224
#define SMEM_FLOATS 22240          // 88,960 bytes -> 2 CTA/SM

// LVC kernel pre-packed in MMA B-fragment order: g_kt[b][l][f], f in [0,6144)
__device__ __align__(16) float g_kt[(size_t)BATCH * KLCH * 6144];
// conv W pre-packed in fragment order (N=32 variant)
__device__ __align__(16) float g_w1f[3072];

__device__ __forceinline__ float tf32r(float x) {
    uint32_t r; asm("cvt.rna.tf32.f32 %0, %1;" : "=r"(r) : "f"(x)); return __uint_as_float(r);
}
__device__ __forceinline__ float fast_tanh(float x) { float r; asm("tanh.approx.f32 %0, %1;" : "=f"(r) : "f"(x)); return r; }
__device__ __forceinline__ float fast_ex2(float x)  { float r; asm("ex2.approx.f32 %0, %1;"  : "=f"(r) : "f"(x)); return r; }
__device__ __forceinline__ float fast_rcp(float x)  { float r; asm("rcp.approx.f32 %0, %1;"  : "=f"(r) : "f"(x)); return r; }

__device__ __forceinline__ uint32_t smem_u32(const void* p) {
    uint32_t a; asm("{ .reg .u64 t; cvta.to.shared.u64 t, %1; cvt.u32.u64 %0, t; }" : "=r"(a) : "l"(p));
    return a;
}
__device__ __forceinline__ void cp_async16(uint32_t dst, const void* src, int src_bytes) {
    asm volatile("cp.async.ca.shared.global [%0], [%1], 16, %2;"
                 :: "r"(dst), "l"(src), "r"(src_bytes) : "memory");
}

__device__ __forceinline__ void mma_tf32(float c[4],
                                         uint32_t a0, uint32_t a1, uint32_t a2, uint32_t a3,
                                         float b0, float b1) {
    asm volatile(
        "mma.sync.aligned.m16n8k8.row.col.f32.tf32.tf32.f32 "
        "{%0,%1,%2,%3}, {%4,%5,%6,%7}, {%8,%9}, {%0,%1,%2,%3};"
        : "+f"(c[0]), "+f"(c[1]), "+f"(c[2]), "+f"(c[3])
        : "r"(a0), "r"(a1), "r"(a2), "r"(a3),
          "r"(__float_as_uint(b0)), "r"(__float_as_uint(b1)));
}

// conv-W element accessor in frag layout (for scalar tail rows)
__device__ __forceinline__ float w1frag_at(const float* wt1f, int c, int kk) {
    int ks = kk >> 3, r = kk & 7, tq = r & 3, hi = r >> 2;
    int tr = c & 7, nt = c >> 3, p = nt >> 1, odd = nt & 1;
    return wt1f[(((ks * 2 + p) * 32 + tq + 4 * tr) << 2) + odd * 2 + hi];
}

// ---------------------------------------------------------------------------
// Prep 1: kernel[b, i, o, k, l] (l fastest) -> g_kt[b][l][frag f]
// ---------------------------------------------------------------------------
__global__ void prep_kernel_tensor(const float* __restrict__ kin) {
    __shared__ float tile[32][33];
    int b  = blockIdx.z;
    int f0 = blockIdx.x * 32;
    int l0 = blockIdx.y * 32;
    int tx = threadIdx.x, ty = threadIdx.y;
    const float* src = kin + (size_t)b * 6144 * 128;
    float*       dst = g_kt + (size_t)b * 128 * 6144;
#pragma unroll
    for (int r = 0; r < 4; r++) {
        int f = f0 + ty + r * 8;
        int sub = f & 3, lane = (f >> 2) & 31, rest = f >> 7;
        int p = rest & 3, ks = rest >> 2;
        int tq = lane & 3, tr = lane >> 2;
        int kk = ks * 8 + tq + (sub & 1) * 4;
        int nt = 2 * p + (sub >> 1);
        int o  = nt * 8 + tr;
        int i  = kk / 3, k = kk - 3 * i;
        int m  = i * 192 + o * 3 + k;
        tile[ty + r * 8][tx] = tf32r(src[(size_t)m * 128 + l0 + tx]);
    }
    __syncthreads();
#pragma unroll
    for (int r = 0; r < 4; r++) {
        int l = l0 + ty + r * 8;
        dst[(size_t)l * 6144 + f0 + tx] = tile[tx][ty + r * 8];
    }
}

// Prep 2: conv_w [co][ci*3+k] -> g_w1f frag order (N=32 variant)
__global__ void prep_w1(const float* __restrict__ conv_w) {
    int f = blockIdx.x * 256 + threadIdx.x;
    if (f < 3072) {
        int sub = f & 3, lane = (f >> 2) & 31, rest = f >> 7;
        int p = rest & 1, ks = rest >> 1;
        int tq = lane & 3, tr = lane >> 2;
        int kk = ks * 8 + tq + (sub & 1) * 4;
        int nt = 2 * p + (sub >> 1);
        int co = nt * 8 + tr;
        g_w1f[f] = tf32r(conv_w[co * 96 + kk]);
    }
}

// ---------------------------------------------------------------------------
// Main fused kernel: one CTA per (256-position chunk, batch); 2 pipelined subs.
// ---------------------------------------------------------------------------
__global__ __launch_bounds__(256, 2)
void lvc_mma_kernel(const float* __restrict__ hidden,
                    const float* __restrict__ bias,
                    const float* __restrict__ conv_w,
                    const float* __restrict__ conv_b,
                    float* __restrict__ out) {
    extern __shared__ float sm[];
    float* wt1f  = sm + OF_WT1;
    float* wt2f  = sm + OF_WT2;
    float* biasS = sm + OF_BIAS;
    float* cbS   = sm + OF_CB;
    float* xsf   = sm + OF_XS;

    const int tid  = threadIdx.x;
    const int wid  = tid >> 5;
    const int lane = tid & 31;
    const int l    = blockIdx.x;      // 256-position chunk 0..127
    const int b    = blockIdx.y;
    const float* hidB = hidden + (size_t)b * HID * LEN;
    const uint32_t sb = smem_u32(sm);

    // ---- prefetch both hs tiles via cp.async (one commit group per sub) ----
#pragma unroll
    for (int s = 0; s < 2; s++) {
        const int s0p = l * 256 + s * 128;
        const uint32_t hbase = sb + (OF_HS0 + s * 4352) * 4;
        for (int idx = tid; idx < 1088; idx += 256) {
            int c = idx / 34, gr = idx - c * 34;
            int g = s0p - 4 + gr * 4;
            // granules never straddle [0, LEN): s0p, LEN both = 0 mod 4
            bool in = (g >= 0) && (g + 4 <= LEN);
            const float* src = hidB + (size_t)c * LEN + (in ? g : 0);
            cp_async16(hbase + (uint32_t)(c * HSS + gr * 4) * 4, src, in ? 16 : 0);
        }
        asm volatile("cp.async.commit_group;" ::: "memory");
    }

    // ---- stage weights (already tf32-rounded + frag-ordered) ----
    {
        const float4* w2s = (const float4*)(g_kt + ((size_t)b * KLCH + l) * 6144);
        float4* w2d = (float4*)wt2f;
        for (int i = tid; i < 1536; i += 256) w2d[i] = w2s[i];
        const float4* w1s = (const float4*)g_w1f;
        float4* w1d = (float4*)wt1f;
        for (int i = tid; i < 768; i += 256) w1d[i] = w1s[i];
    }
    if (tid < 64) biasS[tid] = bias[((size_t)b * 64 + tid) * KLCH + l];
    if (tid < 32) cbS[tid]   = conv_b[tid];

    const int tq = lane & 3;      // threadID_in_group
    const int tr = lane >> 2;     // groupID
    const int m0 = wid * 16;

#pragma unroll
    for (int s = 0; s < 2; s++) {
        const int s0 = l * 256 + s * 128;
        float* hsf = sm + (s ? OF_HS1 : OF_HS0);

        if (s == 0) asm volatile("cp.async.wait_group 1;" ::: "memory");
        else        asm volatile("cp.async.wait_group 0;" ::: "memory");
        __syncthreads();

        // ---- in-place transform: leaky + tf32 round ----
        for (int idx = tid; idx < 1088; idx += 256) {
            int c = idx / 34, gr = idx - c * 34;
            float4* p = (float4*)(hsf + c * HSS + gr * 4);
            float4 t = *p;
            t.x = tf32r((t.x >= 0.f) ? t.x : 0.2f * t.x);
            t.y = tf32r((t.y >= 0.f) ? t.y : 0.2f * t.y);
            t.z = tf32r((t.z >= 0.f) ? t.z : 0.2f * t.z);
            t.w = tf32r((t.w >= 0.f) ? t.w : 0.2f * t.w);
            *p = t;
        }
        __syncthreads();

        // ---- Stage 1: conv GEMM, rows m=0..127 <-> p = s0-1+m ----
        {
            float c1[4][4];
#pragma unroll
            for (int nt = 0; nt < 4; nt++)
#pragma unroll
                for (int j = 0; j < 4; j++) c1[nt][j] = 0.f;

#pragma unroll
            for (int ks = 0; ks < 12; ks++) {
                int kk0 = ks * 8 + tq;
                int ci0 = kk0 / 3, kr0 = kk0 - ci0 * 3;
                int kk1 = kk0 + 4;
                int ci1 = kk1 / 3, kr1 = kk1 - ci1 * 3;
                int base = m0 + tr;
                uint32_t a0 = __float_as_uint(hsf[ci0 * HSS + base     + 3 * kr0]);
                uint32_t a1 = __float_as_uint(hsf[ci0 * HSS + base + 8 + 3 * kr0]);
                uint32_t a2 = __float_as_uint(hsf[ci1 * HSS + base     + 3 * kr1]);
                uint32_t a3 = __float_as_uint(hsf[ci1 * HSS + base + 8 + 3 * kr1]);
                const float4* bp = (const float4*)wt1f + (ks * 2) * 32 + lane;
                float4 q0 = bp[0];
                float4 q1 = bp[32];
                mma_tf32(c1[0], a0, a1, a2, a3, q0.x, q0.y);
                mma_tf32(c1[1], a0, a1, a2, a3, q0.z, q0.w);
                mma_tf32(c1[2], a0, a1, a2, a3, q1.x, q1.y);
                mma_tf32(c1[3], a0, a1, a2, a3, q1.z, q1.w);
            }
            bool z0 = (s0 == 0) && (m0 + tr == 0);
#pragma unroll
            for (int nt = 0; nt < 4; nt++) {
                int c = nt * 8 + 2 * tq;
                float v00 = c1[nt][0] + cbS[c];
                float v01 = c1[nt][1] + cbS[c + 1];
                float v10 = c1[nt][2] + cbS[c];
                float v11 = c1[nt][3] + cbS[c + 1];
                v00 = tf32r((v00 >= 0.f) ? v00 : 0.2f * v00);
                v01 = tf32r((v01 >= 0.f) ? v01 : 0.2f * v01);
                v10 = tf32r((v10 >= 0.f) ? v10 : 0.2f * v10);
                v11 = tf32r((v11 >= 0.f) ? v11 : 0.2f * v11);
                xsf[c       * XSS + m0 + tr]     = z0 ? 0.f : v00;
                xsf[(c + 1) * XSS + m0 + tr]     = z0 ? 0.f : v01;
                xsf[c       * XSS + m0 + tr + 8] = v10;
                xsf[(c + 1) * XSS + m0 + tr + 8] = v11;
            }
        }
        // scalar tail rows m = 128, 129 (p = s0+127, s0+128)
        if (tid >= 128 && tid < 192) {
            int posI = (tid - 128) >> 5, c = tid & 31;
            int m = 128 + posI;
            float acc = 0.f;
            for (int ci = 0; ci < 32; ci++) {
                const float* hr = hsf + ci * HSS + m;
                acc += w1frag_at(wt1f, c, ci * 3 + 0) * hr[0]
                     + w1frag_at(wt1f, c, ci * 3 + 1) * hr[3]
                     + w1frag_at(wt1f, c, ci * 3 + 2) * hr[6];
            }
            float v = acc + cbS[c];
            v = tf32r((v >= 0.f) ? v : 0.2f * v);
            int p = s0 - 1 + m;
            xsf[c * XSS + m] = (p < LEN) ? v : 0.f;
        }
        __syncthreads();

        // ---- Stage 2: LVC GEMM, rows m <-> s = s0+m ----
        float c2[8][4];
#pragma unroll
        for (int nt = 0; nt < 8; nt++)
#pragma unroll
            for (int j = 0; j < 4; j++) c2[nt][j] = 0.f;

#pragma unroll
        for (int ks = 0; ks < 12; ks++) {
            int kk0 = ks * 8 + tq;
            int i0 = kk0 / 3, kr0 = kk0 - i0 * 3;
            int kk1 = kk0 + 4;
            int i1 = kk1 / 3, kr1 = kk1 - i1 * 3;
            int base = m0 + tr;
            uint32_t a0 = __float_as_uint(xsf[i0 * XSS + base     + kr0]);
            uint32_t a1 = __float_as_uint(xsf[i0 * XSS + base + 8 + kr0]);
            uint32_t a2 = __float_as_uint(xsf[i1 * XSS + base     + kr1]);
            uint32_t a3 = __float_as_uint(xsf[i1 * XSS + base + 8 + kr1]);
            const float4* bp = (const float4*)wt2f + (ks * 4) * 32 + lane;
            float4 q0 = bp[0];
            float4 q1 = bp[32];
            float4 q2 = bp[64];
            float4 q3 = bp[96];
            mma_tf32(c2[0], a0, a1, a2, a3, q0.x, q0.y);
            mma_tf32(c2[1], a0, a1, a2, a3, q0.z, q0.w);
            mma_tf32(c2[2], a0, a1, a2, a3, q1.x, q1.y);
            mma_tf32(c2[3], a0, a1, a2, a3, q1.z, q1.w);
            mma_tf32(c2[4], a0, a1, a2, a3, q2.x, q2.y);
            mma_tf32(c2[5], a0, a1, a2, a3, q2.z, q2.w);
            mma_tf32(c2[6], a0, a1, a2, a3, q3.x, q3.y);
            mma_tf32(c2[7], a0, a1, a2, a3, q3.z, q3.w);
        }

        // ---- epilogue straight from fragments (sector-perfect 4B ops) ----
        {
            float* outB = out + (size_t)b * HID * LEN;
            const float LOG2E = 1.4426950408889634f;
#pragma unroll
            for (int nt = 0; nt < 4; nt++) {
                int o = nt * 8 + 2 * tq;
#pragma unroll
                for (int j = 0; j < 4; j++) {
                    int oo = o + (j & 1);
                    int m  = m0 + tr + ((j >> 1) << 3);
                    float gv = c2[nt][j]     + biasS[oo];
                    float hv = c2[nt + 4][j] + biasS[oo + 32];
                    float sig = fast_rcp(1.f + fast_ex2(-LOG2E * gv));
                    float res = hidB[(size_t)oo * LEN + s0 + m];
                    outB[(size_t)oo * LEN + s0 + m] = res + sig * fast_tanh(hv);
                }
            }
        }
    }
}

// ---------------------------------------------------------------------------
extern "C" void kernel_launch(void* const* d_in, const int* in_sizes, int n_in,
                              void* d_out, int out_size) {
    const float* hidden = (const float*)d_in[0];
    const float* kern   = (const float*)d_in[1];
    const float* bias   = (const float*)d_in[2];
    const float* conv_w = (const float*)d_in[3];
    const float* conv_b = (const float*)d_in[4];
    float* out = (float*)d_out;

    prep_w1<<<12, 256>>>(conv_w);
    prep_kernel_tensor<<<dim3(192, 4, 16), dim3(32, 8)>>>(kern);

    int smem_bytes = SMEM_FLOATS * 4;   // 88,960 B
    cudaFuncSetAttribute(lvc_mma_kernel,
                         cudaFuncAttributeMaxDynamicSharedMemorySize, smem_bytes);
    lvc_mma_kernel<<<dim3(KLCH, BATCH), 256, smem_bytes>>>(hidden, bias, conv_w, conv_b, out);
}